// round 11
// baseline (speedup 1.0000x reference)
#include <cuda_runtime.h>
#include <cstdint>

#define NF 32
#define NP 496
#define NU 528
#define NE 32
#define NH 64
#define FS 64
#define BATCH 2048
#define BT 256                 // samples per tile (M)
#define TILES_PER_BLOCK 2
#define GRID_Y 4               // 4 * 2 * 256 = 2048
#define THREADS 512
#define ASTRIDE 68             // A plane row stride (floats), 68%32=4 -> conflict-free frags
#define WSTRIDE 68             // W^T plane row stride

// ---------------- device scratch ----------------
__device__ __align__(128) float g_T1[NP * FS * NH];
__device__ __align__(128) float g_T2[NP * FS * NH];
__device__ __align__(128) float g_Tm[NF * FS * NH];
__device__ float g_gw2p[NP * NH];
__device__ float g_gw2m[NF * NH];
__device__ float g_C;

__device__ __forceinline__ float smoothz(float z) {
    if (z <= -0.5f) return 0.0f;
    if (z >= 0.5f) return 1.0f;
    return -2.0f * z * z * z + 1.5f * z + 0.5f;
}

__device__ __forceinline__ uint32_t tf32_hi(float f) {
    uint32_t u;
    asm("cvt.rna.tf32.f32 %0, %1;" : "=r"(u) : "f"(f));
    return u;
}

__device__ __forceinline__ void mma_tf32(float& d0, float& d1, float& d2, float& d3,
                                         uint32_t a0, uint32_t a1, uint32_t a2, uint32_t a3,
                                         uint32_t b0, uint32_t b1) {
    asm("mma.sync.aligned.m16n8k8.row.col.f32.tf32.tf32.f32 "
        "{%0,%1,%2,%3}, {%4,%5,%6,%7}, {%8,%9}, {%0,%1,%2,%3};"
        : "+f"(d0), "+f"(d1), "+f"(d2), "+f"(d3)
        : "r"(a0), "r"(a1), "r"(a2), "r"(a3), "r"(b0), "r"(b1));
}

// ---------------- kernel 1: precompute layer-0 lookup tables ----------------
__global__ __launch_bounds__(256) void precompute_tables(
    const float* __restrict__ emb,
    const int* __restrict__ pairs_list,
    const int* __restrict__ offsets,
    const float* __restrict__ pw0, const float* __restrict__ pb0,
    const float* __restrict__ mw0, const float* __restrict__ mb0)
{
    __shared__ float Es[FS * NE];
    __shared__ float Ws[NE * NH];

    int bid = blockIdx.x;
    int tid = threadIdx.x;

    const float* wsrc;
    const float* bias = nullptr;
    float* dst;
    int embRow0;

    if (bid < NP) {
        int p = bid;
        embRow0 = offsets[pairs_list[2 * p]];
        wsrc = pw0 + (p * 64 + 0) * NH;
        bias = pb0 + p * NH;
        dst = g_T1 + p * FS * NH;
    } else if (bid < 2 * NP) {
        int p = bid - NP;
        embRow0 = offsets[pairs_list[2 * p + 1]];
        wsrc = pw0 + (p * 64 + 32) * NH;
        dst = g_T2 + p * FS * NH;
    } else {
        int f = bid - 2 * NP;
        embRow0 = f * FS;
        wsrc = mw0 + f * NE * NH;
        bias = mb0 + f * NH;
        dst = g_Tm + f * FS * NH;
    }

    for (int i = tid; i < FS * NE; i += 256) Es[i] = emb[embRow0 * NE + i];
    for (int i = tid; i < NE * NH; i += 256) Ws[i] = wsrc[i];
    __syncthreads();

    int v = tid >> 2;
    int j0 = (tid & 3) * 16;
    float acc[16];
#pragma unroll
    for (int t = 0; t < 16; t++) acc[t] = bias ? bias[j0 + t] : 0.0f;
    for (int e = 0; e < NE; e++) {
        float a = Es[v * NE + e];
#pragma unroll
        for (int t = 0; t < 16; t++) acc[t] = fmaf(a, Ws[e * NH + j0 + t], acc[t]);
    }
#pragma unroll
    for (int t = 0; t < 16; t++) dst[v * NH + j0 + t] = acc[t];
}

// ---------------- kernel 2: gated layer-2 weights + bias constant ----------------
__global__ void precompute_gates(
    const float* __restrict__ pw2, const float* __restrict__ pb2, const float* __restrict__ zp,
    const float* __restrict__ mw2, const float* __restrict__ mb2, const float* __restrict__ zm)
{
    int i = blockIdx.x * 256 + threadIdx.x;
    if (i < NP * NH) g_gw2p[i] = pw2[i] * smoothz(zp[i >> 6]);
    if (i < NF * NH) g_gw2m[i] = mw2[i] * smoothz(zm[i >> 6]);
    if (i == 0) {
        float c = 0.0f;
        for (int p = 0; p < NP; p++) c += pb2[p] * smoothz(zp[p]);
        for (int f = 0; f < NF; f++) c += mb2[f] * smoothz(zm[f]);
        g_C = c;
    }
}

// ---------------- kernel 3: init output with constant ----------------
__global__ void init_out(float* __restrict__ out) {
    out[blockIdx.x * 256 + threadIdx.x] = g_C;
}

// ---------------- kernel 4: fused main pass (mma.sync tf32 split) ---------------
// 512 threads = 16 warps. Tile: 256 samples x 64 cols. Warp (g = w>>1, h = w&1):
// rows 32g..32g+31 (two m16 tiles), cols 32h..32h+31 (four n8 tiles).
// smem float offsets:
#define SM_AHI 0
#define SM_ALO (SM_AHI + BT * ASTRIDE)       // 17408
#define SM_WHI (SM_ALO + BT * ASTRIDE)       // 34816  (W^T [n][k] stride 68)
#define SM_WLO (SM_WHI + NH * WSTRIDE)       // 39168
#define SM_B1  (SM_WLO + NH * WSTRIDE)       // 43520
#define SM_G2  (SM_B1 + NH)                  // 43584
#define SM_FLOATS (SM_G2 + NH)               // 43648 floats = 174592 B

__global__ __launch_bounds__(THREADS, 1) void fused_pass(
    const int* __restrict__ mains, const int* __restrict__ pairs,
    const float* __restrict__ pw1, const float* __restrict__ mw1,
    const float* __restrict__ pb1, const float* __restrict__ mb1,
    float* __restrict__ out)
{
    extern __shared__ float sm[];
    uint32_t* AHI = (uint32_t*)(sm + SM_AHI);
    uint32_t* ALO = (uint32_t*)(sm + SM_ALO);
    uint32_t* WHI = (uint32_t*)(sm + SM_WHI);
    uint32_t* WLO = (uint32_t*)(sm + SM_WLO);
    float* b1s = sm + SM_B1;
    float* g2s = sm + SM_G2;

    int unit = blockIdx.x;
    int tid = threadIdx.x;
    int lane = tid & 31;
    int w = tid >> 5;
    int g = w >> 1;            // 0..7 row group
    int h = w & 1;             // 0/1 col half
    bool isPair = unit < NP;

    const float *t1src, *t2src = nullptr, *w1src, *b1src, *g2src;
    if (isPair) {
        t1src = g_T1 + unit * FS * NH;
        t2src = g_T2 + unit * FS * NH;
        w1src = pw1 + unit * NH * NH;
        b1src = pb1 + unit * NH;
        g2src = g_gw2p + unit * NH;
    } else {
        int f = unit - NP;
        t1src = g_Tm + f * FS * NH;
        w1src = mw1 + f * NH * NH;
        b1src = mb1 + f * NH;
        g2src = g_gw2m + f * NH;
    }

    // ---- stage W^T hi/lo planes (once per block): W1[k][n] -> WT[n][k] ----
    for (int i = tid; i < NH * NH; i += THREADS) {
        int k = i >> 6, n = i & 63;
        float v = w1src[i];
        uint32_t hi = tf32_hi(v);
        float lof = v - __uint_as_float(hi);
        WHI[n * WSTRIDE + k] = hi;
        WLO[n * WSTRIDE + k] = tf32_hi(lof);
    }
    if (tid < NH) { b1s[tid] = b1src[tid]; g2s[tid] = g2src[tid]; }

    // fragment address bases (constant across tiles)
    int aOff0 = (32 * g + (lane >> 2)) * ASTRIDE + (lane & 3);          // m-tile 0
    int aOff1 = (32 * g + 16 + (lane >> 2)) * ASTRIDE + (lane & 3);     // m-tile 1
    int bOff[4];
#pragma unroll
    for (int j = 0; j < 4; j++)
        bOff[j] = (32 * h + 8 * j + (lane >> 2)) * WSTRIDE + (lane & 3);

    int s = tid >> 1;          // gather: sample within tile
    int half = tid & 1;        // gather: k half (32 each)

    for (int t = 0; t < TILES_PER_BLOCK; t++) {
        int base = (blockIdx.y * TILES_PER_BLOCK + t) * BT;
        __syncthreads();       // W planes visible (t=0) / previous tile consumed (t>0)

        // ---- gather from global tables -> A hi/lo planes ([m][k], tf32 split) ----
        {
            int b = base + s;
            const float4* r1;
            const float4* r2 = nullptr;
            if (isPair) {
                int2 ii = ((const int2*)pairs)[b * NP + unit];
                r1 = (const float4*)(t1src + ii.x * NH) + half * 8;
                r2 = (const float4*)(t2src + ii.y * NH) + half * 8;
            } else {
                int i1 = mains[b * NF + (unit - NP)];
                r1 = (const float4*)(t1src + i1 * NH) + half * 8;
            }
#pragma unroll
            for (int q = 0; q < 8; q++) {
                float4 a = r1[q];
                float v0, v1, v2, v3;
                if (isPair) {
                    float4 c = r2[q];
                    v0 = fmaxf(a.x + c.x, 0.0f); v1 = fmaxf(a.y + c.y, 0.0f);
                    v2 = fmaxf(a.z + c.z, 0.0f); v3 = fmaxf(a.w + c.w, 0.0f);
                } else {
                    v0 = fmaxf(a.x, 0.0f); v1 = fmaxf(a.y, 0.0f);
                    v2 = fmaxf(a.z, 0.0f); v3 = fmaxf(a.w, 0.0f);
                }
                uint32_t h0 = tf32_hi(v0), h1 = tf32_hi(v1), h2 = tf32_hi(v2), h3 = tf32_hi(v3);
                uint32_t l0 = tf32_hi(v0 - __uint_as_float(h0));
                uint32_t l1 = tf32_hi(v1 - __uint_as_float(h1));
                uint32_t l2 = tf32_hi(v2 - __uint_as_float(h2));
                uint32_t l3 = tf32_hi(v3 - __uint_as_float(h3));
                int idx = s * ASTRIDE + half * 32 + 4 * q;
                *(uint4*)&AHI[idx] = make_uint4(h0, h1, h2, h3);
                *(uint4*)&ALO[idx] = make_uint4(l0, l1, l2, l3);
            }
        }
        __syncthreads();

        // ---- GEMM: 3-term tf32 split, m16n8k8 mma ----
        float acc[2][4][4];
#pragma unroll
        for (int mt = 0; mt < 2; mt++)
#pragma unroll
            for (int j = 0; j < 4; j++)
#pragma unroll
                for (int r = 0; r < 4; r++) acc[mt][j][r] = 0.0f;

#pragma unroll 2
        for (int ks = 0; ks < 8; ks++) {
            int k0 = ks * 8;
            uint32_t ah[2][4], al[2][4];
#pragma unroll
            for (int mt = 0; mt < 2; mt++) {
                int ao = (mt ? aOff1 : aOff0) + k0;
                ah[mt][0] = AHI[ao];
                ah[mt][1] = AHI[ao + 8 * ASTRIDE];
                ah[mt][2] = AHI[ao + 4];
                ah[mt][3] = AHI[ao + 8 * ASTRIDE + 4];
                al[mt][0] = ALO[ao];
                al[mt][1] = ALO[ao + 8 * ASTRIDE];
                al[mt][2] = ALO[ao + 4];
                al[mt][3] = ALO[ao + 8 * ASTRIDE + 4];
            }
#pragma unroll
            for (int j = 0; j < 4; j++) {
                int bo = bOff[j] + k0;
                uint32_t bh0 = WHI[bo], bh1 = WHI[bo + 4];
                uint32_t bl0 = WLO[bo], bl1 = WLO[bo + 4];
#pragma unroll
                for (int mt = 0; mt < 2; mt++) {
                    mma_tf32(acc[mt][j][0], acc[mt][j][1], acc[mt][j][2], acc[mt][j][3],
                             ah[mt][0], ah[mt][1], ah[mt][2], ah[mt][3], bh0, bh1);
                    mma_tf32(acc[mt][j][0], acc[mt][j][1], acc[mt][j][2], acc[mt][j][3],
                             al[mt][0], al[mt][1], al[mt][2], al[mt][3], bh0, bh1);
                    mma_tf32(acc[mt][j][0], acc[mt][j][1], acc[mt][j][2], acc[mt][j][3],
                             ah[mt][0], ah[mt][1], ah[mt][2], ah[mt][3], bl0, bl1);
                }
            }
        }

        // ---- epilogue: +b1, relu, dot g2, lane-reduce, atomicAdd ----
#pragma unroll
        for (int mt = 0; mt < 2; mt++) {
            float s0 = 0.0f, s1 = 0.0f;
#pragma unroll
            for (int j = 0; j < 4; j++) {
                int col = 32 * h + 8 * j + 2 * (lane & 3);
                float bb0 = b1s[col], bb1 = b1s[col + 1];
                float gg0 = g2s[col], gg1 = g2s[col + 1];
                s0 = fmaf(fmaxf(acc[mt][j][0] + bb0, 0.0f), gg0, s0);
                s0 = fmaf(fmaxf(acc[mt][j][1] + bb1, 0.0f), gg1, s0);
                s1 = fmaf(fmaxf(acc[mt][j][2] + bb0, 0.0f), gg0, s1);
                s1 = fmaf(fmaxf(acc[mt][j][3] + bb1, 0.0f), gg1, s1);
            }
            s0 += __shfl_xor_sync(0xffffffffu, s0, 1);
            s0 += __shfl_xor_sync(0xffffffffu, s0, 2);
            s1 += __shfl_xor_sync(0xffffffffu, s1, 1);
            s1 += __shfl_xor_sync(0xffffffffu, s1, 2);
            if ((lane & 3) == 0) {
                int r = base + 32 * g + 16 * mt + (lane >> 2);
                atomicAdd(&out[r], s0);
                atomicAdd(&out[r + 8], s1);
            }
        }
    }
}

// ---------------- launch ----------------
extern "C" void kernel_launch(void* const* d_in, const int* in_sizes, int n_in,
                              void* d_out, int out_size)
{
    const int*   mains      = (const int*)d_in[0];
    const int*   pairs      = (const int*)d_in[1];
    const int*   pairs_list = (const int*)d_in[2];
    const int*   offsets    = (const int*)d_in[3];
    const float* embedding  = (const float*)d_in[4];
    const float* mw0        = (const float*)d_in[5];
    const float* mw1        = (const float*)d_in[6];
    const float* mw2        = (const float*)d_in[7];
    const float* mb0        = (const float*)d_in[8];
    const float* mb1        = (const float*)d_in[9];
    const float* mb2        = (const float*)d_in[10];
    const float* pw0        = (const float*)d_in[11];
    const float* pw1        = (const float*)d_in[12];
    const float* pw2        = (const float*)d_in[13];
    const float* pb0        = (const float*)d_in[14];
    const float* pb1        = (const float*)d_in[15];
    const float* pb2        = (const float*)d_in[16];
    const float* z_main     = (const float*)d_in[17];
    const float* z_pairs    = (const float*)d_in[18];
    float* out = (float*)d_out;

    static int attr_set = 0;
    const int smem_bytes = SM_FLOATS * (int)sizeof(float);
    if (!attr_set) {
        cudaFuncSetAttribute(fused_pass, cudaFuncAttributeMaxDynamicSharedMemorySize, smem_bytes);
        attr_set = 1;
    }

    precompute_tables<<<2 * NP + NF, 256>>>(embedding, pairs_list, offsets,
                                            pw0, pb0, mw0, mb0);
    precompute_gates<<<(NP * NH + 255) / 256, 256>>>(pw2, pb2, z_pairs, mw2, mb2, z_main);
    init_out<<<BATCH / 256, 256>>>(out);

    dim3 grid(NU, GRID_Y);
    fused_pass<<<grid, THREADS, smem_bytes>>>(mains, pairs, pw1, mw1, pb1, mb1, out);
}

// round 12
// speedup vs baseline: 1.3190x; 1.3190x over previous
#include <cuda_runtime.h>
#include <cstdint>

#define NF 32
#define NP 496
#define NU 528
#define NE 32
#define NH 64
#define FS 64
#define BATCH 2048
#define BT 128                 // samples per tile (M)
#define TILES_PER_BLOCK 4
#define GRID_Y 4               // 4 * 4 * 128 = 2048
#define THREADS 256
#define AST 36                 // A plane row stride in bf16x2 words (32 + 4 pad)
#define WST 36                 // W^T plane row stride in bf16x2 words

// ---------------- device scratch ----------------
__device__ __align__(128) float g_T1[NP * FS * NH];
__device__ __align__(128) float g_T2[NP * FS * NH];
__device__ __align__(128) float g_Tm[NF * FS * NH];
__device__ float g_gw2p[NP * NH];
__device__ float g_gw2m[NF * NH];
__device__ float g_C;

__device__ __forceinline__ float smoothz(float z) {
    if (z <= -0.5f) return 0.0f;
    if (z >= 0.5f) return 1.0f;
    return -2.0f * z * z * z + 1.5f * z + 0.5f;
}

// pack two fp32 into bf16x2 hi-part and residual lo-part words
__device__ __forceinline__ void bsplit2(float a0, float a1, uint32_t& hi, uint32_t& lo) {
    asm("cvt.rn.bf16x2.f32 %0, %2, %1;" : "=r"(hi) : "f"(a0), "f"(a1));
    float h0 = __uint_as_float(hi << 16);
    float h1 = __uint_as_float(hi & 0xffff0000u);
    float l0 = a0 - h0, l1 = a1 - h1;
    asm("cvt.rn.bf16x2.f32 %0, %2, %1;" : "=r"(lo) : "f"(l0), "f"(l1));
}

__device__ __forceinline__ void mma_bf16(float& d0, float& d1, float& d2, float& d3,
                                         uint32_t a0, uint32_t a1, uint32_t a2, uint32_t a3,
                                         uint32_t b0, uint32_t b1) {
    asm("mma.sync.aligned.m16n8k16.row.col.f32.bf16.bf16.f32 "
        "{%0,%1,%2,%3}, {%4,%5,%6,%7}, {%8,%9}, {%0,%1,%2,%3};"
        : "+f"(d0), "+f"(d1), "+f"(d2), "+f"(d3)
        : "r"(a0), "r"(a1), "r"(a2), "r"(a3), "r"(b0), "r"(b1));
}

// ---------------- kernel 1: precompute layer-0 lookup tables ----------------
__global__ __launch_bounds__(256) void precompute_tables(
    const float* __restrict__ emb,
    const int* __restrict__ pairs_list,
    const int* __restrict__ offsets,
    const float* __restrict__ pw0, const float* __restrict__ pb0,
    const float* __restrict__ mw0, const float* __restrict__ mb0)
{
    __shared__ float Es[FS * NE];
    __shared__ float Ws[NE * NH];

    int bid = blockIdx.x;
    int tid = threadIdx.x;

    const float* wsrc;
    const float* bias = nullptr;
    float* dst;
    int embRow0;

    if (bid < NP) {
        int p = bid;
        embRow0 = offsets[pairs_list[2 * p]];
        wsrc = pw0 + (p * 64 + 0) * NH;
        bias = pb0 + p * NH;
        dst = g_T1 + p * FS * NH;
    } else if (bid < 2 * NP) {
        int p = bid - NP;
        embRow0 = offsets[pairs_list[2 * p + 1]];
        wsrc = pw0 + (p * 64 + 32) * NH;
        dst = g_T2 + p * FS * NH;
    } else {
        int f = bid - 2 * NP;
        embRow0 = f * FS;
        wsrc = mw0 + f * NE * NH;
        bias = mb0 + f * NH;
        dst = g_Tm + f * FS * NH;
    }

    for (int i = tid; i < FS * NE; i += 256) Es[i] = emb[embRow0 * NE + i];
    for (int i = tid; i < NE * NH; i += 256) Ws[i] = wsrc[i];
    __syncthreads();

    int v = tid >> 2;
    int j0 = (tid & 3) * 16;
    float acc[16];
#pragma unroll
    for (int t = 0; t < 16; t++) acc[t] = bias ? bias[j0 + t] : 0.0f;
    for (int e = 0; e < NE; e++) {
        float a = Es[v * NE + e];
#pragma unroll
        for (int t = 0; t < 16; t++) acc[t] = fmaf(a, Ws[e * NH + j0 + t], acc[t]);
    }
#pragma unroll
    for (int t = 0; t < 16; t++) dst[v * NH + j0 + t] = acc[t];
}

// ---------------- kernel 2: gated layer-2 weights + bias constant ----------------
__global__ void precompute_gates(
    const float* __restrict__ pw2, const float* __restrict__ pb2, const float* __restrict__ zp,
    const float* __restrict__ mw2, const float* __restrict__ mb2, const float* __restrict__ zm)
{
    int i = blockIdx.x * 256 + threadIdx.x;
    if (i < NP * NH) g_gw2p[i] = pw2[i] * smoothz(zp[i >> 6]);
    if (i < NF * NH) g_gw2m[i] = mw2[i] * smoothz(zm[i >> 6]);
    if (i == 0) {
        float c = 0.0f;
        for (int p = 0; p < NP; p++) c += pb2[p] * smoothz(zp[p]);
        for (int f = 0; f < NF; f++) c += mb2[f] * smoothz(zm[f]);
        g_C = c;
    }
}

// ---------------- kernel 3: init output with constant ----------------
__global__ void init_out(float* __restrict__ out) {
    out[blockIdx.x * 256 + threadIdx.x] = g_C;
}

// ---------------- kernel 4: fused main pass (mma.sync bf16 m16n8k16 split) ------
// 256 threads = 8 warps, 3 CTAs/SM. Tile: 128 samples x 64 cols.
// Warp (g = w>>1 in 0..3, h = w&1): rows 32g..32g+31 (two m16 tiles),
// cols 32h..32h+31 (four n8 tiles). A planes [m][kw] bf16x2 stride 36;
// W^T planes [n][kw] bf16x2 stride 36. All fragment LDS conflict-free.
#define SM_AHI 0
#define SM_ALO (SM_AHI + BT * AST)           //  4608 words
#define SM_WHI (SM_ALO + BT * AST)           //  9216
#define SM_WLO (SM_WHI + NH * WST)           // 11520
#define SM_B1  (SM_WLO + NH * WST)           // 13824
#define SM_G2  (SM_B1 + NH)                  // 13888
#define SM_WORDS (SM_G2 + NH)                // 13952 words = 55808 B -> 3 CTAs/SM

__global__ __launch_bounds__(THREADS, 3) void fused_pass(
    const int* __restrict__ mains, const int* __restrict__ pairs,
    const float* __restrict__ pw1, const float* __restrict__ mw1,
    const float* __restrict__ pb1, const float* __restrict__ mb1,
    float* __restrict__ out)
{
    extern __shared__ uint32_t smw[];
    uint32_t* AHI = smw + SM_AHI;
    uint32_t* ALO = smw + SM_ALO;
    uint32_t* WHI = smw + SM_WHI;
    uint32_t* WLO = smw + SM_WLO;
    float* b1s = (float*)(smw + SM_B1);
    float* g2s = (float*)(smw + SM_G2);

    int unit = blockIdx.x;
    int tid = threadIdx.x;
    int lane = tid & 31;
    int w = tid >> 5;
    int g = w >> 1;            // 0..3 row group
    int h = w & 1;             // 0/1 col half
    bool isPair = unit < NP;

    const float *t1src, *t2src = nullptr, *w1src, *b1src, *g2src;
    if (isPair) {
        t1src = g_T1 + unit * FS * NH;
        t2src = g_T2 + unit * FS * NH;
        w1src = pw1 + unit * NH * NH;
        b1src = pb1 + unit * NH;
        g2src = g_gw2p + unit * NH;
    } else {
        int f = unit - NP;
        t1src = g_Tm + f * FS * NH;
        w1src = mw1 + f * NH * NH;
        b1src = mb1 + f * NH;
        g2src = g_gw2m + f * NH;
    }

    // ---- stage W^T hi/lo planes: W1[k][n] -> WT[n][kw] bf16x2 ----
    for (int i = tid; i < NH * (NH / 2); i += THREADS) {
        int n = i >> 5, kw = i & 31;
        float v0 = w1src[(2 * kw) * NH + n];
        float v1 = w1src[(2 * kw + 1) * NH + n];
        uint32_t hi, lo;
        bsplit2(v0, v1, hi, lo);
        WHI[n * WST + kw] = hi;
        WLO[n * WST + kw] = lo;
    }
    if (tid < NH) { b1s[tid] = b1src[tid]; g2s[tid] = g2src[tid]; }

    // fragment word-address bases (constant across tiles)
    int aOff0 = (32 * g + (lane >> 2)) * AST + (lane & 3);          // m-tile 0
    int aOff1 = (32 * g + 16 + (lane >> 2)) * AST + (lane & 3);     // m-tile 1
    int bOff[4];
#pragma unroll
    for (int j = 0; j < 4; j++)
        bOff[j] = (32 * h + 8 * j + (lane >> 2)) * WST + (lane & 3);

    int s = tid >> 1;          // gather: sample within tile (0..127)
    int half = tid & 1;        // gather: k half (32 values)

    for (int t = 0; t < TILES_PER_BLOCK; t++) {
        int base = (blockIdx.y * TILES_PER_BLOCK + t) * BT;
        __syncthreads();       // W planes visible (t=0) / prev tile A consumed (t>0)

        // ---- gather from global tables -> A hi/lo planes (bf16x2 split) ----
        {
            int b = base + s;
            const float4* r1;
            const float4* r2 = nullptr;
            if (isPair) {
                int2 ii = ((const int2*)pairs)[b * NP + unit];
                r1 = (const float4*)(t1src + ii.x * NH) + half * 8;
                r2 = (const float4*)(t2src + ii.y * NH) + half * 8;
            } else {
                int i1 = mains[b * NF + (unit - NP)];
                r1 = (const float4*)(t1src + i1 * NH) + half * 8;
            }
#pragma unroll
            for (int qq = 0; qq < 4; qq++) {
                float4 a0 = r1[2 * qq];
                float4 a1 = r1[2 * qq + 1];
                float v[8];
                if (isPair) {
                    float4 c0 = r2[2 * qq];
                    float4 c1 = r2[2 * qq + 1];
                    v[0] = fmaxf(a0.x + c0.x, 0.0f); v[1] = fmaxf(a0.y + c0.y, 0.0f);
                    v[2] = fmaxf(a0.z + c0.z, 0.0f); v[3] = fmaxf(a0.w + c0.w, 0.0f);
                    v[4] = fmaxf(a1.x + c1.x, 0.0f); v[5] = fmaxf(a1.y + c1.y, 0.0f);
                    v[6] = fmaxf(a1.z + c1.z, 0.0f); v[7] = fmaxf(a1.w + c1.w, 0.0f);
                } else {
                    v[0] = fmaxf(a0.x, 0.0f); v[1] = fmaxf(a0.y, 0.0f);
                    v[2] = fmaxf(a0.z, 0.0f); v[3] = fmaxf(a0.w, 0.0f);
                    v[4] = fmaxf(a1.x, 0.0f); v[5] = fmaxf(a1.y, 0.0f);
                    v[6] = fmaxf(a1.z, 0.0f); v[7] = fmaxf(a1.w, 0.0f);
                }
                uint32_t hw[4], lw[4];
#pragma unroll
                for (int q = 0; q < 4; q++) bsplit2(v[2 * q], v[2 * q + 1], hw[q], lw[q]);
                int idx = s * AST + half * 16 + 4 * qq;
                *(uint4*)&AHI[idx] = make_uint4(hw[0], hw[1], hw[2], hw[3]);
                *(uint4*)&ALO[idx] = make_uint4(lw[0], lw[1], lw[2], lw[3]);
            }
        }
        __syncthreads();

        // ---- GEMM: 3-term bf16 split, m16n8k16 ----
        float acc[2][4][4];
#pragma unroll
        for (int mt = 0; mt < 2; mt++)
#pragma unroll
            for (int j = 0; j < 4; j++)
#pragma unroll
                for (int r = 0; r < 4; r++) acc[mt][j][r] = 0.0f;

#pragma unroll
        for (int ks = 0; ks < 4; ks++) {         // k chunks of 16 (8 words)
            int k0 = ks * 8;
            uint32_t ah[2][4], al[2][4];
#pragma unroll
            for (int mt = 0; mt < 2; mt++) {
                int ao = (mt ? aOff1 : aOff0) + k0;
                ah[mt][0] = AHI[ao];
                ah[mt][1] = AHI[ao + 8 * AST];
                ah[mt][2] = AHI[ao + 4];
                ah[mt][3] = AHI[ao + 8 * AST + 4];
                al[mt][0] = ALO[ao];
                al[mt][1] = ALO[ao + 8 * AST];
                al[mt][2] = ALO[ao + 4];
                al[mt][3] = ALO[ao + 8 * AST + 4];
            }
#pragma unroll
            for (int j = 0; j < 4; j++) {
                int bo = bOff[j] + k0;
                uint32_t bh0 = WHI[bo], bh1 = WHI[bo + 4];
                uint32_t bl0 = WLO[bo], bl1 = WLO[bo + 4];
#pragma unroll
                for (int mt = 0; mt < 2; mt++) {
                    mma_bf16(acc[mt][j][0], acc[mt][j][1], acc[mt][j][2], acc[mt][j][3],
                             ah[mt][0], ah[mt][1], ah[mt][2], ah[mt][3], bh0, bh1);
                    mma_bf16(acc[mt][j][0], acc[mt][j][1], acc[mt][j][2], acc[mt][j][3],
                             al[mt][0], al[mt][1], al[mt][2], al[mt][3], bh0, bh1);
                    mma_bf16(acc[mt][j][0], acc[mt][j][1], acc[mt][j][2], acc[mt][j][3],
                             ah[mt][0], ah[mt][1], ah[mt][2], ah[mt][3], bl0, bl1);
                }
            }
        }

        // ---- epilogue: +b1, relu, dot g2, lane-reduce, atomicAdd ----
#pragma unroll
        for (int mt = 0; mt < 2; mt++) {
            float s0 = 0.0f, s1 = 0.0f;
#pragma unroll
            for (int j = 0; j < 4; j++) {
                int col = 32 * h + 8 * j + 2 * (lane & 3);
                float bb0 = b1s[col], bb1 = b1s[col + 1];
                float gg0 = g2s[col], gg1 = g2s[col + 1];
                s0 = fmaf(fmaxf(acc[mt][j][0] + bb0, 0.0f), gg0, s0);
                s0 = fmaf(fmaxf(acc[mt][j][1] + bb1, 0.0f), gg1, s0);
                s1 = fmaf(fmaxf(acc[mt][j][2] + bb0, 0.0f), gg0, s1);
                s1 = fmaf(fmaxf(acc[mt][j][3] + bb1, 0.0f), gg1, s1);
            }
            s0 += __shfl_xor_sync(0xffffffffu, s0, 1);
            s0 += __shfl_xor_sync(0xffffffffu, s0, 2);
            s1 += __shfl_xor_sync(0xffffffffu, s1, 1);
            s1 += __shfl_xor_sync(0xffffffffu, s1, 2);
            if ((lane & 3) == 0) {
                int r = base + 32 * g + 16 * mt + (lane >> 2);
                atomicAdd(&out[r], s0);
                atomicAdd(&out[r + 8], s1);
            }
        }
    }
}

// ---------------- launch ----------------
extern "C" void kernel_launch(void* const* d_in, const int* in_sizes, int n_in,
                              void* d_out, int out_size)
{
    const int*   mains      = (const int*)d_in[0];
    const int*   pairs      = (const int*)d_in[1];
    const int*   pairs_list = (const int*)d_in[2];
    const int*   offsets    = (const int*)d_in[3];
    const float* embedding  = (const float*)d_in[4];
    const float* mw0        = (const float*)d_in[5];
    const float* mw1        = (const float*)d_in[6];
    const float* mw2        = (const float*)d_in[7];
    const float* mb0        = (const float*)d_in[8];
    const float* mb1        = (const float*)d_in[9];
    const float* mb2        = (const float*)d_in[10];
    const float* pw0        = (const float*)d_in[11];
    const float* pw1        = (const float*)d_in[12];
    const float* pw2        = (const float*)d_in[13];
    const float* pb0        = (const float*)d_in[14];
    const float* pb1        = (const float*)d_in[15];
    const float* pb2        = (const float*)d_in[16];
    const float* z_main     = (const float*)d_in[17];
    const float* z_pairs    = (const float*)d_in[18];
    float* out = (float*)d_out;

    static int attr_set = 0;
    const int smem_bytes = SM_WORDS * (int)sizeof(uint32_t);
    if (!attr_set) {
        cudaFuncSetAttribute(fused_pass, cudaFuncAttributeMaxDynamicSharedMemorySize, smem_bytes);
        attr_set = 1;
    }

    precompute_tables<<<2 * NP + NF, 256>>>(embedding, pairs_list, offsets,
                                            pw0, pb0, mw0, mb0);
    precompute_gates<<<(NP * NH + 255) / 256, 256>>>(pw2, pb2, z_pairs, mw2, mb2, z_main);
    init_out<<<BATCH / 256, 256>>>(out);

    dim3 grid(NU, GRID_Y);
    fused_pass<<<grid, THREADS, smem_bytes>>>(mains, pairs, pw1, mw1, pb1, mb1, out);
}

// round 13
// speedup vs baseline: 1.8115x; 1.3734x over previous
#include <cuda_runtime.h>
#include <cstdint>

#define NF 32
#define NP 496
#define NU 528
#define NE 32
#define NH 64
#define FS 64
#define BATCH 2048
#define BT 128                 // samples per tile (M)
#define TILES_PER_BLOCK 4
#define GRID_Y 4               // 4 * 4 * 128 = 2048
#define THREADS 256
#define AST 36                 // A plane row stride in bf16x2 words
#define WST 40                 // W^T plane row stride in bf16x2 words (interleaved)

// ---------------- device scratch ----------------
__device__ __align__(128) float g_T1[NP * FS * NH];
__device__ __align__(128) float g_T2[NP * FS * NH];
__device__ __align__(128) float g_Tm[NF * FS * NH];
__device__ float g_gw2p[NP * NH];
__device__ float g_gw2m[NF * NH];
__device__ float g_C;

__device__ __forceinline__ float smoothz(float z) {
    if (z <= -0.5f) return 0.0f;
    if (z >= 0.5f) return 1.0f;
    return -2.0f * z * z * z + 1.5f * z + 0.5f;
}

// pack two fp32 into bf16x2 hi-part and residual lo-part words
__device__ __forceinline__ void bsplit2(float a0, float a1, uint32_t& hi, uint32_t& lo) {
    asm("cvt.rn.bf16x2.f32 %0, %2, %1;" : "=r"(hi) : "f"(a0), "f"(a1));
    float h0 = __uint_as_float(hi << 16);
    float h1 = __uint_as_float(hi & 0xffff0000u);
    float l0 = a0 - h0, l1 = a1 - h1;
    asm("cvt.rn.bf16x2.f32 %0, %2, %1;" : "=r"(lo) : "f"(l0), "f"(l1));
}

__device__ __forceinline__ void mma_bf16(float& d0, float& d1, float& d2, float& d3,
                                         uint32_t a0, uint32_t a1, uint32_t a2, uint32_t a3,
                                         uint32_t b0, uint32_t b1) {
    asm("mma.sync.aligned.m16n8k16.row.col.f32.bf16.bf16.f32 "
        "{%0,%1,%2,%3}, {%4,%5,%6,%7}, {%8,%9}, {%0,%1,%2,%3};"
        : "+f"(d0), "+f"(d1), "+f"(d2), "+f"(d3)
        : "r"(a0), "r"(a1), "r"(a2), "r"(a3), "r"(b0), "r"(b1));
}

// ---------------- kernel 1: precompute layer-0 lookup tables ----------------
__global__ __launch_bounds__(256) void precompute_tables(
    const float* __restrict__ emb,
    const int* __restrict__ pairs_list,
    const int* __restrict__ offsets,
    const float* __restrict__ pw0, const float* __restrict__ pb0,
    const float* __restrict__ mw0, const float* __restrict__ mb0)
{
    __shared__ float Es[FS * NE];
    __shared__ float Ws[NE * NH];

    int bid = blockIdx.x;
    int tid = threadIdx.x;

    const float* wsrc;
    const float* bias = nullptr;
    float* dst;
    int embRow0;

    if (bid < NP) {
        int p = bid;
        embRow0 = offsets[pairs_list[2 * p]];
        wsrc = pw0 + (p * 64 + 0) * NH;
        bias = pb0 + p * NH;
        dst = g_T1 + p * FS * NH;
    } else if (bid < 2 * NP) {
        int p = bid - NP;
        embRow0 = offsets[pairs_list[2 * p + 1]];
        wsrc = pw0 + (p * 64 + 32) * NH;
        dst = g_T2 + p * FS * NH;
    } else {
        int f = bid - 2 * NP;
        embRow0 = f * FS;
        wsrc = mw0 + f * NE * NH;
        bias = mb0 + f * NH;
        dst = g_Tm + f * FS * NH;
    }

    for (int i = tid; i < FS * NE; i += 256) Es[i] = emb[embRow0 * NE + i];
    for (int i = tid; i < NE * NH; i += 256) Ws[i] = wsrc[i];
    __syncthreads();

    int v = tid >> 2;
    int j0 = (tid & 3) * 16;
    float acc[16];
#pragma unroll
    for (int t = 0; t < 16; t++) acc[t] = bias ? bias[j0 + t] : 0.0f;
    for (int e = 0; e < NE; e++) {
        float a = Es[v * NE + e];
#pragma unroll
        for (int t = 0; t < 16; t++) acc[t] = fmaf(a, Ws[e * NH + j0 + t], acc[t]);
    }
#pragma unroll
    for (int t = 0; t < 16; t++) dst[v * NH + j0 + t] = acc[t];
}

// ---------------- kernel 2: gated layer-2 weights + bias constant ----------------
__global__ void precompute_gates(
    const float* __restrict__ pw2, const float* __restrict__ pb2, const float* __restrict__ zp,
    const float* __restrict__ mw2, const float* __restrict__ mb2, const float* __restrict__ zm)
{
    int i = blockIdx.x * 256 + threadIdx.x;
    if (i < NP * NH) g_gw2p[i] = pw2[i] * smoothz(zp[i >> 6]);
    if (i < NF * NH) g_gw2m[i] = mw2[i] * smoothz(zm[i >> 6]);
    if (i == 0) {
        float c = 0.0f;
        for (int p = 0; p < NP; p++) c += pb2[p] * smoothz(zp[p]);
        for (int f = 0; f < NF; f++) c += mb2[f] * smoothz(zm[f]);
        g_C = c;
    }
}

// ---------------- kernel 3: init output with constant ----------------
__global__ void init_out(float* __restrict__ out) {
    out[blockIdx.x * 256 + threadIdx.x] = g_C;
}

// ---------------- kernel 4: fused main pass (bf16 m16n8k16 split, lean gather) --
// 256 threads = 8 warps, 3 CTAs/SM. Tile: 128 samples x 64 cols.
// Gather: one sample per warp per round (16 rounds); lane reads float2 (k pair)
//   -> warp request = 2 full lines; store 1 word/plane at s*36+lane (bank-perfect).
// W^T planes k-interleaved (kw -> (kw&~7) + 2(kw&3) + ((kw>>2)&1), stride 40)
//   so fragment pair (kw, kw+4) is one conflict-free LDS.64.
#define SM_AHI 0
#define SM_ALO (SM_AHI + BT * AST)           //  4608 words
#define SM_WHI (SM_ALO + BT * AST)           //  9216
#define SM_WLO (SM_WHI + NH * WST)           // 11776
#define SM_B1  (SM_WLO + NH * WST)           // 14336
#define SM_G2  (SM_B1 + NH)                  // 14400
#define SM_WORDS (SM_G2 + NH)                // 14464 words = 57856 B -> 3 CTAs/SM

__global__ __launch_bounds__(THREADS, 3) void fused_pass(
    const int* __restrict__ mains, const int* __restrict__ pairs,
    const float* __restrict__ pw1, const float* __restrict__ mw1,
    const float* __restrict__ pb1, const float* __restrict__ mb1,
    float* __restrict__ out)
{
    extern __shared__ uint32_t smw[];
    uint32_t* AHI = smw + SM_AHI;
    uint32_t* ALO = smw + SM_ALO;
    uint32_t* WHI = smw + SM_WHI;
    uint32_t* WLO = smw + SM_WLO;
    float* b1s = (float*)(smw + SM_B1);
    float* g2s = (float*)(smw + SM_G2);

    int unit = blockIdx.x;
    int tid = threadIdx.x;
    int lane = tid & 31;
    int w = tid >> 5;
    int g = w >> 1;            // 0..3 row group
    int h = w & 1;             // 0/1 col half
    bool isPair = unit < NP;

    const float *t1src, *t2src = nullptr, *w1src, *b1src, *g2src;
    if (isPair) {
        t1src = g_T1 + unit * FS * NH;
        t2src = g_T2 + unit * FS * NH;
        w1src = pw1 + unit * NH * NH;
        b1src = pb1 + unit * NH;
        g2src = g_gw2p + unit * NH;
    } else {
        int f = unit - NP;
        t1src = g_Tm + f * FS * NH;
        w1src = mw1 + f * NH * NH;
        b1src = mb1 + f * NH;
        g2src = g_gw2m + f * NH;
    }

    // ---- stage W^T hi/lo planes (k-interleaved): W1[k][n] -> WT[n][tau(kw)] ----
    for (int i = tid; i < NH * (NH / 2); i += THREADS) {
        int n = i >> 5, kw = i & 31;
        float v0 = w1src[(2 * kw) * NH + n];
        float v1 = w1src[(2 * kw + 1) * NH + n];
        uint32_t hi, lo;
        bsplit2(v0, v1, hi, lo);
        int tau = (kw & ~7) + ((kw & 3) << 1) + ((kw >> 2) & 1);
        WHI[n * WST + tau] = hi;
        WLO[n * WST + tau] = lo;
    }
    if (tid < NH) { b1s[tid] = b1src[tid]; g2s[tid] = g2src[tid]; }

    // fragment word-address bases (constant across tiles)
    int aOff0 = (32 * g + (lane >> 2)) * AST + (lane & 3);          // m-tile 0
    int aOff1 = (32 * g + 16 + (lane >> 2)) * AST + (lane & 3);     // m-tile 1
    int bOff[4];
#pragma unroll
    for (int j = 0; j < 4; j++)
        bOff[j] = (32 * h + 8 * j + (lane >> 2)) * WST + ((lane & 3) << 1);

    for (int t = 0; t < TILES_PER_BLOCK; t++) {
        int base = (blockIdx.y * TILES_PER_BLOCK + t) * BT;
        __syncthreads();       // W planes visible (t=0) / prev tile A consumed (t>0)

        // ---- gather: one sample per warp per round; lane = k-pair ----
        if (isPair) {
#pragma unroll
            for (int r = 0; r < 16; r++) {
                int s = r * 8 + w;
                int b = base + s;
                int2 ii = ((const int2*)pairs)[b * NP + unit];
                float2 a = ((const float2*)(t1src + ii.x * NH))[lane];
                float2 d = ((const float2*)(t2src + ii.y * NH))[lane];
                float v0 = fmaxf(a.x + d.x, 0.0f);
                float v1 = fmaxf(a.y + d.y, 0.0f);
                uint32_t hi, lo;
                bsplit2(v0, v1, hi, lo);
                AHI[s * AST + lane] = hi;
                ALO[s * AST + lane] = lo;
            }
        } else {
            int f = unit - NP;
#pragma unroll
            for (int r = 0; r < 16; r++) {
                int s = r * 8 + w;
                int b = base + s;
                int i1 = mains[b * NF + f];
                float2 a = ((const float2*)(t1src + i1 * NH))[lane];
                float v0 = fmaxf(a.x, 0.0f);
                float v1 = fmaxf(a.y, 0.0f);
                uint32_t hi, lo;
                bsplit2(v0, v1, hi, lo);
                AHI[s * AST + lane] = hi;
                ALO[s * AST + lane] = lo;
            }
        }
        __syncthreads();

        // ---- GEMM: 3-term bf16 split, m16n8k16 ----
        float acc[2][4][4];
#pragma unroll
        for (int mt = 0; mt < 2; mt++)
#pragma unroll
            for (int j = 0; j < 4; j++)
#pragma unroll
                for (int r = 0; r < 4; r++) acc[mt][j][r] = 0.0f;

#pragma unroll
        for (int ks = 0; ks < 4; ks++) {         // k chunks of 16 (8 words)
            int k0 = ks * 8;
            uint32_t ah[2][4], al[2][4];
#pragma unroll
            for (int mt = 0; mt < 2; mt++) {
                int ao = (mt ? aOff1 : aOff0) + k0;
                ah[mt][0] = AHI[ao];
                ah[mt][1] = AHI[ao + 8 * AST];
                ah[mt][2] = AHI[ao + 4];
                ah[mt][3] = AHI[ao + 8 * AST + 4];
                al[mt][0] = ALO[ao];
                al[mt][1] = ALO[ao + 8 * AST];
                al[mt][2] = ALO[ao + 4];
                al[mt][3] = ALO[ao + 8 * AST + 4];
            }
#pragma unroll
            for (int j = 0; j < 4; j++) {
                int bo = bOff[j] + k0;
                uint2 bh = *(const uint2*)&WHI[bo];
                uint2 bl = *(const uint2*)&WLO[bo];
#pragma unroll
                for (int mt = 0; mt < 2; mt++) {
                    mma_bf16(acc[mt][j][0], acc[mt][j][1], acc[mt][j][2], acc[mt][j][3],
                             ah[mt][0], ah[mt][1], ah[mt][2], ah[mt][3], bh.x, bh.y);
                    mma_bf16(acc[mt][j][0], acc[mt][j][1], acc[mt][j][2], acc[mt][j][3],
                             al[mt][0], al[mt][1], al[mt][2], al[mt][3], bh.x, bh.y);
                    mma_bf16(acc[mt][j][0], acc[mt][j][1], acc[mt][j][2], acc[mt][j][3],
                             ah[mt][0], ah[mt][1], ah[mt][2], ah[mt][3], bl.x, bl.y);
                }
            }
        }

        // ---- epilogue: +b1, relu, dot g2, lane-reduce, atomicAdd ----
#pragma unroll
        for (int mt = 0; mt < 2; mt++) {
            float s0 = 0.0f, s1 = 0.0f;
#pragma unroll
            for (int j = 0; j < 4; j++) {
                int col = 32 * h + 8 * j + 2 * (lane & 3);
                float bb0 = b1s[col], bb1 = b1s[col + 1];
                float gg0 = g2s[col], gg1 = g2s[col + 1];
                s0 = fmaf(fmaxf(acc[mt][j][0] + bb0, 0.0f), gg0, s0);
                s0 = fmaf(fmaxf(acc[mt][j][1] + bb1, 0.0f), gg1, s0);
                s1 = fmaf(fmaxf(acc[mt][j][2] + bb0, 0.0f), gg0, s1);
                s1 = fmaf(fmaxf(acc[mt][j][3] + bb1, 0.0f), gg1, s1);
            }
            s0 += __shfl_xor_sync(0xffffffffu, s0, 1);
            s0 += __shfl_xor_sync(0xffffffffu, s0, 2);
            s1 += __shfl_xor_sync(0xffffffffu, s1, 1);
            s1 += __shfl_xor_sync(0xffffffffu, s1, 2);
            if ((lane & 3) == 0) {
                int r = base + 32 * g + 16 * mt + (lane >> 2);
                atomicAdd(&out[r], s0);
                atomicAdd(&out[r + 8], s1);
            }
        }
    }
}

// ---------------- launch ----------------
extern "C" void kernel_launch(void* const* d_in, const int* in_sizes, int n_in,
                              void* d_out, int out_size)
{
    const int*   mains      = (const int*)d_in[0];
    const int*   pairs      = (const int*)d_in[1];
    const int*   pairs_list = (const int*)d_in[2];
    const int*   offsets    = (const int*)d_in[3];
    const float* embedding  = (const float*)d_in[4];
    const float* mw0        = (const float*)d_in[5];
    const float* mw1        = (const float*)d_in[6];
    const float* mw2        = (const float*)d_in[7];
    const float* mb0        = (const float*)d_in[8];
    const float* mb1        = (const float*)d_in[9];
    const float* mb2        = (const float*)d_in[10];
    const float* pw0        = (const float*)d_in[11];
    const float* pw1        = (const float*)d_in[12];
    const float* pw2        = (const float*)d_in[13];
    const float* pb0        = (const float*)d_in[14];
    const float* pb1        = (const float*)d_in[15];
    const float* pb2        = (const float*)d_in[16];
    const float* z_main     = (const float*)d_in[17];
    const float* z_pairs    = (const float*)d_in[18];
    float* out = (float*)d_out;

    static int attr_set = 0;
    const int smem_bytes = SM_WORDS * (int)sizeof(uint32_t);
    if (!attr_set) {
        cudaFuncSetAttribute(fused_pass, cudaFuncAttributeMaxDynamicSharedMemorySize, smem_bytes);
        attr_set = 1;
    }

    precompute_tables<<<2 * NP + NF, 256>>>(embedding, pairs_list, offsets,
                                            pw0, pb0, mw0, mb0);
    precompute_gates<<<(NP * NH + 255) / 256, 256>>>(pw2, pb2, z_pairs, mw2, mb2, z_main);
    init_out<<<BATCH / 256, 256>>>(out);

    dim3 grid(NU, GRID_Y);
    fused_pass<<<grid, THREADS, smem_bytes>>>(mains, pairs, pw1, mw1, pb1, mb1, out);
}

// round 15
// speedup vs baseline: 2.0162x; 1.1130x over previous
#include <cuda_runtime.h>
#include <cstdint>

#define NF 32
#define NP 496
#define NU 528
#define NE 32
#define NH 64
#define FS 64
#define BATCH 2048
#define BT 128                 // samples per tile (M)
#define TILES_PER_BLOCK 4
#define GRID_Y 4               // 4 * 4 * 128 = 2048
#define THREADS 256
#define AST2 36                // A combined plane row stride (uint2 units)
#define WST4 20                // B combined plane row stride (uint4 units)

// ---------------- device scratch ----------------
__device__ __align__(128) float g_T1[NP * FS * NH];
__device__ __align__(128) float g_T2[NP * FS * NH];
__device__ __align__(128) float g_Tm[NF * FS * NH];
__device__ float g_gw2p[NP * NH];
__device__ float g_gw2m[NF * NH];
__device__ float g_C;

__device__ __forceinline__ float smoothz(float z) {
    if (z <= -0.5f) return 0.0f;
    if (z >= 0.5f) return 1.0f;
    return -2.0f * z * z * z + 1.5f * z + 0.5f;
}

// pack two fp32 into bf16x2 hi-part and residual lo-part words
__device__ __forceinline__ void bsplit2(float a0, float a1, uint32_t& hi, uint32_t& lo) {
    asm("cvt.rn.bf16x2.f32 %0, %2, %1;" : "=r"(hi) : "f"(a0), "f"(a1));
    float h0 = __uint_as_float(hi << 16);
    float h1 = __uint_as_float(hi & 0xffff0000u);
    float l0 = a0 - h0, l1 = a1 - h1;
    asm("cvt.rn.bf16x2.f32 %0, %2, %1;" : "=r"(lo) : "f"(l0), "f"(l1));
}

__device__ __forceinline__ void mma_bf16(float& d0, float& d1, float& d2, float& d3,
                                         uint32_t a0, uint32_t a1, uint32_t a2, uint32_t a3,
                                         uint32_t b0, uint32_t b1) {
    asm("mma.sync.aligned.m16n8k16.row.col.f32.bf16.bf16.f32 "
        "{%0,%1,%2,%3}, {%4,%5,%6,%7}, {%8,%9}, {%0,%1,%2,%3};"
        : "+f"(d0), "+f"(d1), "+f"(d2), "+f"(d3)
        : "r"(a0), "r"(a1), "r"(a2), "r"(a3), "r"(b0), "r"(b1));
}

// ---------------- kernel 1: precompute layer-0 lookup tables ----------------
__global__ __launch_bounds__(256) void precompute_tables(
    const float* __restrict__ emb,
    const int* __restrict__ pairs_list,
    const int* __restrict__ offsets,
    const float* __restrict__ pw0, const float* __restrict__ pb0,
    const float* __restrict__ mw0, const float* __restrict__ mb0)
{
    __shared__ float Es[FS * NE];
    __shared__ float Ws[NE * NH];

    int bid = blockIdx.x;
    int tid = threadIdx.x;

    const float* wsrc;
    const float* bias = nullptr;
    float* dst;
    int embRow0;

    if (bid < NP) {
        int p = bid;
        embRow0 = offsets[pairs_list[2 * p]];
        wsrc = pw0 + (p * 64 + 0) * NH;
        bias = pb0 + p * NH;
        dst = g_T1 + p * FS * NH;
    } else if (bid < 2 * NP) {
        int p = bid - NP;
        embRow0 = offsets[pairs_list[2 * p + 1]];
        wsrc = pw0 + (p * 64 + 32) * NH;
        dst = g_T2 + p * FS * NH;
    } else {
        int f = bid - 2 * NP;
        embRow0 = f * FS;
        wsrc = mw0 + f * NE * NH;
        bias = mb0 + f * NH;
        dst = g_Tm + f * FS * NH;
    }

    for (int i = tid; i < FS * NE; i += 256) Es[i] = emb[embRow0 * NE + i];
    for (int i = tid; i < NE * NH; i += 256) Ws[i] = wsrc[i];
    __syncthreads();

    int v = tid >> 2;
    int j0 = (tid & 3) * 16;
    float acc[16];
#pragma unroll
    for (int t = 0; t < 16; t++) acc[t] = bias ? bias[j0 + t] : 0.0f;
    for (int e = 0; e < NE; e++) {
        float a = Es[v * NE + e];
#pragma unroll
        for (int t = 0; t < 16; t++) acc[t] = fmaf(a, Ws[e * NH + j0 + t], acc[t]);
    }
#pragma unroll
    for (int t = 0; t < 16; t++) dst[v * NH + j0 + t] = acc[t];
}

// ---------------- kernel 2: gated layer-2 weights + bias constant ----------------
__global__ void precompute_gates(
    const float* __restrict__ pw2, const float* __restrict__ pb2, const float* __restrict__ zp,
    const float* __restrict__ mw2, const float* __restrict__ mb2, const float* __restrict__ zm)
{
    int i = blockIdx.x * 256 + threadIdx.x;
    if (i < NP * NH) g_gw2p[i] = pw2[i] * smoothz(zp[i >> 6]);
    if (i < NF * NH) g_gw2m[i] = mw2[i] * smoothz(zm[i >> 6]);

    // block 0: parallel deterministic reduction for the constant term
    if (blockIdx.x == 0) {
        __shared__ float red[256];
        int t = threadIdx.x;
        float c = 0.0f;
        for (int p = t; p < NP; p += 256) c += pb2[p] * smoothz(zp[p]);
        for (int f = t; f < NF; f += 256) c += mb2[f] * smoothz(zm[f]);
        red[t] = c;
        __syncthreads();
        for (int o = 128; o > 0; o >>= 1) {
            if (t < o) red[t] += red[t + o];
            __syncthreads();
        }
        if (t == 0) g_C = red[0];
    }
}

// ---------------- kernel 3: init output with constant ----------------
__global__ void init_out(float* __restrict__ out) {
    out[blockIdx.x * 256 + threadIdx.x] = g_C;
}

// ---------------- kernel 4: fused main pass (bf16 m16n8k16, interleaved planes) -
// 256 threads = 8 warps, 3 CTAs/SM. Tile: 128 samples x 64 cols.
// A combined plane: uint2 {hi,lo} per (s,kw), stride 36 uint2 (conflict-free).
// B combined plane: uint4 {hi(k),hi(k+4),lo(k),lo(k+4)} per (n,kg,c), stride 20 uint4.
#define SM_AC 0
#define SM_BC (SM_AC + BT * AST2 * 2)        //  9216 words
#define SM_B1 (SM_BC + NH * WST4 * 4)        // 14336
#define SM_G2 (SM_B1 + NH)                   // 14400
#define SM_WORDS (SM_G2 + NH)                // 14464 words = 57856 B -> 3 CTAs/SM

__global__ __launch_bounds__(THREADS, 3) void fused_pass(
    const int* __restrict__ mains, const int* __restrict__ pairs,
    const float* __restrict__ pw1, const float* __restrict__ mw1,
    const float* __restrict__ pb1, const float* __restrict__ mb1,
    float* __restrict__ out)
{
    extern __shared__ uint32_t smw[];
    uint2* AC = (uint2*)(smw + SM_AC);
    uint4* BC = (uint4*)(smw + SM_BC);
    uint32_t* BCw = smw + SM_BC;
    float* b1s = (float*)(smw + SM_B1);
    float* g2s = (float*)(smw + SM_G2);

    int unit = blockIdx.x;
    int tid = threadIdx.x;
    int lane = tid & 31;
    int w = tid >> 5;
    int g = w >> 1;            // 0..3 row group
    int h = w & 1;             // 0/1 col half
    bool isPair = unit < NP;

    const float *t1src, *t2src = nullptr, *w1src, *b1src, *g2src;
    if (isPair) {
        t1src = g_T1 + unit * FS * NH;
        t2src = g_T2 + unit * FS * NH;
        w1src = pw1 + unit * NH * NH;
        b1src = pb1 + unit * NH;
        g2src = g_gw2p + unit * NH;
    } else {
        int f = unit - NP;
        t1src = g_Tm + f * FS * NH;
        w1src = mw1 + f * NH * NH;
        b1src = mb1 + f * NH;
        g2src = g_gw2m + f * NH;
    }

    // ---- stage B combined plane: W1[k][n] -> {hi(k),hi(k+4),lo(k),lo(k+4)} ----
    for (int i = tid; i < NH * (NH / 2); i += THREADS) {
        int n = i >> 5, kw = i & 31;
        float v0 = w1src[(2 * kw) * NH + n];
        float v1 = w1src[(2 * kw + 1) * NH + n];
        uint32_t hi, lo;
        bsplit2(v0, v1, hi, lo);
        int kg = kw >> 3, c = kw & 3, sel = (kw >> 2) & 1;
        int base = (n * WST4 + kg * 4 + c) * 4;
        BCw[base + sel] = hi;
        BCw[base + 2 + sel] = lo;
    }
    if (tid < NH) { b1s[tid] = b1src[tid]; g2s[tid] = g2src[tid]; }

    // fragment address bases (constant across tiles)
    int aOff0 = (32 * g + (lane >> 2)) * AST2 + (lane & 3);          // m-tile 0
    int aOff1 = (32 * g + 16 + (lane >> 2)) * AST2 + (lane & 3);     // m-tile 1
    int bOff[4];
#pragma unroll
    for (int j = 0; j < 4; j++)
        bOff[j] = (32 * h + 8 * j + (lane >> 2)) * WST4 + (lane & 3);

    for (int t = 0; t < TILES_PER_BLOCK; t++) {
        int base = (blockIdx.y * TILES_PER_BLOCK + t) * BT;
        __syncthreads();       // B plane visible (t=0) / prev tile A consumed (t>0)

        // ---- gather: one sample per warp per round; lane = k-pair ----
        if (isPair) {
#pragma unroll
            for (int r = 0; r < 16; r++) {
                int s = r * 8 + w;
                int b = base + s;
                int2 ii = ((const int2*)pairs)[b * NP + unit];
                float2 a = ((const float2*)(t1src + ii.x * NH))[lane];
                float2 d = ((const float2*)(t2src + ii.y * NH))[lane];
                float v0 = fmaxf(a.x + d.x, 0.0f);
                float v1 = fmaxf(a.y + d.y, 0.0f);
                uint32_t hi, lo;
                bsplit2(v0, v1, hi, lo);
                AC[s * AST2 + lane] = make_uint2(hi, lo);
            }
        } else {
            int f = unit - NP;
#pragma unroll
            for (int r = 0; r < 16; r++) {
                int s = r * 8 + w;
                int b = base + s;
                int i1 = mains[b * NF + f];
                float2 a = ((const float2*)(t1src + i1 * NH))[lane];
                float v0 = fmaxf(a.x, 0.0f);
                float v1 = fmaxf(a.y, 0.0f);
                uint32_t hi, lo;
                bsplit2(v0, v1, hi, lo);
                AC[s * AST2 + lane] = make_uint2(hi, lo);
            }
        }
        __syncthreads();

        // ---- GEMM: 3-term bf16 split, m16n8k16 ----
        float acc[2][4][4];
#pragma unroll
        for (int mt = 0; mt < 2; mt++)
#pragma unroll
            for (int j = 0; j < 4; j++)
#pragma unroll
                for (int r = 0; r < 4; r++) acc[mt][j][r] = 0.0f;

#pragma unroll
        for (int ks = 0; ks < 4; ks++) {         // k chunks of 16 (8 kw words)
            int k0 = ks * 8;
            uint32_t ah[2][4], al[2][4];
#pragma unroll
            for (int mt = 0; mt < 2; mt++) {
                int ao = (mt ? aOff1 : aOff0) + k0;
                uint2 v0 = AC[ao];
                uint2 v1 = AC[ao + 8 * AST2];
                uint2 v2 = AC[ao + 4];
                uint2 v3 = AC[ao + 8 * AST2 + 4];
                ah[mt][0] = v0.x; al[mt][0] = v0.y;
                ah[mt][1] = v1.x; al[mt][1] = v1.y;
                ah[mt][2] = v2.x; al[mt][2] = v2.y;
                ah[mt][3] = v3.x; al[mt][3] = v3.y;
            }
#pragma unroll
            for (int j = 0; j < 4; j++) {
                uint4 bv = BC[bOff[j] + ks * 4];
#pragma unroll
                for (int mt = 0; mt < 2; mt++) {
                    mma_bf16(acc[mt][j][0], acc[mt][j][1], acc[mt][j][2], acc[mt][j][3],
                             ah[mt][0], ah[mt][1], ah[mt][2], ah[mt][3], bv.x, bv.y);
                    mma_bf16(acc[mt][j][0], acc[mt][j][1], acc[mt][j][2], acc[mt][j][3],
                             al[mt][0], al[mt][1], al[mt][2], al[mt][3], bv.x, bv.y);
                    mma_bf16(acc[mt][j][0], acc[mt][j][1], acc[mt][j][2], acc[mt][j][3],
                             ah[mt][0], ah[mt][1], ah[mt][2], ah[mt][3], bv.z, bv.w);
                }
            }
        }

        // ---- epilogue: +b1, relu, dot g2, lane-reduce, atomicAdd ----
#pragma unroll
        for (int mt = 0; mt < 2; mt++) {
            float s0 = 0.0f, s1 = 0.0f;
#pragma unroll
            for (int j = 0; j < 4; j++) {
                int col = 32 * h + 8 * j + 2 * (lane & 3);
                float bb0 = b1s[col], bb1 = b1s[col + 1];
                float gg0 = g2s[col], gg1 = g2s[col + 1];
                s0 = fmaf(fmaxf(acc[mt][j][0] + bb0, 0.0f), gg0, s0);
                s0 = fmaf(fmaxf(acc[mt][j][1] + bb1, 0.0f), gg1, s0);
                s1 = fmaf(fmaxf(acc[mt][j][2] + bb0, 0.0f), gg0, s1);
                s1 = fmaf(fmaxf(acc[mt][j][3] + bb1, 0.0f), gg1, s1);
            }
            s0 += __shfl_xor_sync(0xffffffffu, s0, 1);
            s0 += __shfl_xor_sync(0xffffffffu, s0, 2);
            s1 += __shfl_xor_sync(0xffffffffu, s1, 1);
            s1 += __shfl_xor_sync(0xffffffffu, s1, 2);
            if ((lane & 3) == 0) {
                int r = base + 32 * g + 16 * mt + (lane >> 2);
                atomicAdd(&out[r], s0);
                atomicAdd(&out[r + 8], s1);
            }
        }
    }
}

// ---------------- launch ----------------
extern "C" void kernel_launch(void* const* d_in, const int* in_sizes, int n_in,
                              void* d_out, int out_size)
{
    const int*   mains      = (const int*)d_in[0];
    const int*   pairs      = (const int*)d_in[1];
    const int*   pairs_list = (const int*)d_in[2];
    const int*   offsets    = (const int*)d_in[3];
    const float* embedding  = (const float*)d_in[4];
    const float* mw0        = (const float*)d_in[5];
    const float* mw1        = (const float*)d_in[6];
    const float* mw2        = (const float*)d_in[7];
    const float* mb0        = (const float*)d_in[8];
    const float* mb1        = (const float*)d_in[9];
    const float* mb2        = (const float*)d_in[10];
    const float* pw0        = (const float*)d_in[11];
    const float* pw1        = (const float*)d_in[12];
    const float* pw2        = (const float*)d_in[13];
    const float* pb0        = (const float*)d_in[14];
    const float* pb1        = (const float*)d_in[15];
    const float* pb2        = (const float*)d_in[16];
    const float* z_main     = (const float*)d_in[17];
    const float* z_pairs    = (const float*)d_in[18];
    float* out = (float*)d_out;

    static int attr_set = 0;
    const int smem_bytes = SM_WORDS * (int)sizeof(uint32_t);
    if (!attr_set) {
        cudaFuncSetAttribute(fused_pass, cudaFuncAttributeMaxDynamicSharedMemorySize, smem_bytes);
        attr_set = 1;
    }

    precompute_tables<<<2 * NP + NF, 256>>>(embedding, pairs_list, offsets,
                                            pw0, pb0, mw0, mb0);
    precompute_gates<<<(NP * NH + 255) / 256, 256>>>(pw2, pb2, z_pairs, mw2, mb2, z_main);
    init_out<<<BATCH / 256, 256>>>(out);

    dim3 grid(NU, GRID_Y);
    fused_pass<<<grid, THREADS, smem_bytes>>>(mains, pairs, pw1, mw1, pb1, mb1, out);
}

// round 16
// speedup vs baseline: 2.1598x; 1.0712x over previous
#include <cuda_runtime.h>
#include <cstdint>

#define NF 32
#define NP 496
#define NU 528
#define NE 32
#define NH 64
#define FS 64
#define BATCH 2048
#define BT 128                 // samples per tile (M)
#define TILES_PER_BLOCK 4
#define GRID_Y 4               // 4 * 4 * 128 = 2048
#define THREADS 256
#define AST2 36                // A combined plane row stride (uint2 units)
#define WST4 20                // B combined plane row stride (uint4 units)

// ---------------- device scratch ----------------
__device__ __align__(128) float g_T1[NP * FS * NH];
__device__ __align__(128) float g_T2[NP * FS * NH];
__device__ __align__(128) float g_Tm[NF * FS * NH];
__device__ float g_gw2p[NP * NH];
__device__ float g_gw2m[NF * NH];

__device__ __forceinline__ float smoothz(float z) {
    if (z <= -0.5f) return 0.0f;
    if (z >= 0.5f) return 1.0f;
    return -2.0f * z * z * z + 1.5f * z + 0.5f;
}

// pack two fp32 into bf16x2 hi-part and residual lo-part words
__device__ __forceinline__ void bsplit2(float a0, float a1, uint32_t& hi, uint32_t& lo) {
    asm("cvt.rn.bf16x2.f32 %0, %2, %1;" : "=r"(hi) : "f"(a0), "f"(a1));
    float h0 = __uint_as_float(hi << 16);
    float h1 = __uint_as_float(hi & 0xffff0000u);
    float l0 = a0 - h0, l1 = a1 - h1;
    asm("cvt.rn.bf16x2.f32 %0, %2, %1;" : "=r"(lo) : "f"(l0), "f"(l1));
}

__device__ __forceinline__ void mma_bf16(float& d0, float& d1, float& d2, float& d3,
                                         uint32_t a0, uint32_t a1, uint32_t a2, uint32_t a3,
                                         uint32_t b0, uint32_t b1) {
    asm("mma.sync.aligned.m16n8k16.row.col.f32.bf16.bf16.f32 "
        "{%0,%1,%2,%3}, {%4,%5,%6,%7}, {%8,%9}, {%0,%1,%2,%3};"
        : "+f"(d0), "+f"(d1), "+f"(d2), "+f"(d3)
        : "r"(a0), "r"(a1), "r"(a2), "r"(a3), "r"(b0), "r"(b1));
}

// ---------------- kernel 1: merged prelude ----------------
// blocks 0..1023: layer-0 lookup tables (vectorized I/O)
// block 1024: gated layer-2 weights + bias constant + output init
__global__ __launch_bounds__(256) void prelude(
    const float* __restrict__ emb,
    const int* __restrict__ pairs_list,
    const int* __restrict__ offsets,
    const float* __restrict__ pw0, const float* __restrict__ pb0,
    const float* __restrict__ mw0, const float* __restrict__ mb0,
    const float* __restrict__ pw2, const float* __restrict__ pb2,
    const float* __restrict__ zp,
    const float* __restrict__ mw2, const float* __restrict__ mb2,
    const float* __restrict__ zm,
    float* __restrict__ out)
{
    int bid = blockIdx.x;
    int tid = threadIdx.x;

    if (bid >= 2 * NP + NF) {
        // ---- gates + constant + out init ----
        __shared__ float red[256];
        for (int i = tid; i < NP * NH; i += 256) g_gw2p[i] = pw2[i] * smoothz(zp[i >> 6]);
        for (int i = tid; i < NF * NH; i += 256) g_gw2m[i] = mw2[i] * smoothz(zm[i >> 6]);
        float c = 0.0f;
        for (int p = tid; p < NP; p += 256) c += pb2[p] * smoothz(zp[p]);
        for (int f = tid; f < NF; f += 256) c += mb2[f] * smoothz(zm[f]);
        red[tid] = c;
        __syncthreads();
        for (int o = 128; o > 0; o >>= 1) {
            if (tid < o) red[tid] += red[tid + o];
            __syncthreads();
        }
        float C = red[0];
        for (int i = tid; i < BATCH; i += 256) out[i] = C;
        return;
    }

    // ---- table block ----
    __shared__ float Es[FS * NE];
    __shared__ float Ws[NE * NH];

    const float* wsrc;
    const float* bias = nullptr;
    float* dst;
    int embRow0;

    if (bid < NP) {
        int p = bid;
        embRow0 = offsets[pairs_list[2 * p]];
        wsrc = pw0 + (p * 64 + 0) * NH;
        bias = pb0 + p * NH;
        dst = g_T1 + p * FS * NH;
    } else if (bid < 2 * NP) {
        int p = bid - NP;
        embRow0 = offsets[pairs_list[2 * p + 1]];
        wsrc = pw0 + (p * 64 + 32) * NH;
        dst = g_T2 + p * FS * NH;
    } else {
        int f = bid - 2 * NP;
        embRow0 = f * FS;
        wsrc = mw0 + f * NE * NH;
        bias = mb0 + f * NH;
        dst = g_Tm + f * FS * NH;
    }

    {
        const float4* es = (const float4*)(emb + embRow0 * NE);
        for (int i = tid; i < FS * NE / 4; i += 256) ((float4*)Es)[i] = es[i];
        const float4* ws = (const float4*)wsrc;
        for (int i = tid; i < NE * NH / 4; i += 256) ((float4*)Ws)[i] = ws[i];
    }
    __syncthreads();

    int v = tid >> 2;
    int j0 = (tid & 3) * 16;
    float acc[16];
#pragma unroll
    for (int t = 0; t < 16; t++) acc[t] = bias ? bias[j0 + t] : 0.0f;
    for (int e = 0; e < NE; e++) {
        float a = Es[v * NE + e];
#pragma unroll
        for (int t = 0; t < 16; t++) acc[t] = fmaf(a, Ws[e * NH + j0 + t], acc[t]);
    }
#pragma unroll
    for (int q = 0; q < 4; q++) {
        float4 vv = make_float4(acc[4 * q], acc[4 * q + 1], acc[4 * q + 2], acc[4 * q + 3]);
        *(float4*)&dst[v * NH + j0 + 4 * q] = vv;
    }
}

// ---------------- kernel 2: fused main pass (bf16 m16n8k16, interleaved planes) -
// 256 threads = 8 warps, 3 CTAs/SM. Tile: 128 samples x 64 cols.
// A combined plane: uint2 {hi,lo} per (s,kw), stride 36 uint2 (conflict-free).
// B combined plane: uint4 {hi(k),hi(k+4),lo(k),lo(k+4)} per (n,kg,c), stride 20 uint4.
#define SM_AC 0
#define SM_BC (SM_AC + BT * AST2 * 2)        //  9216 words
#define SM_B1 (SM_BC + NH * WST4 * 4)        // 14336
#define SM_G2 (SM_B1 + NH)                   // 14400
#define SM_WORDS (SM_G2 + NH)                // 14464 words = 57856 B -> 3 CTAs/SM

__global__ __launch_bounds__(THREADS, 3) void fused_pass(
    const int* __restrict__ mains, const int* __restrict__ pairs,
    const float* __restrict__ pw1, const float* __restrict__ mw1,
    const float* __restrict__ pb1, const float* __restrict__ mb1,
    float* __restrict__ out)
{
    extern __shared__ uint32_t smw[];
    uint2* AC = (uint2*)(smw + SM_AC);
    uint4* BC = (uint4*)(smw + SM_BC);
    uint32_t* BCw = smw + SM_BC;
    float* b1s = (float*)(smw + SM_B1);
    float* g2s = (float*)(smw + SM_G2);

    int unit = blockIdx.x;
    int tid = threadIdx.x;
    int lane = tid & 31;
    int w = tid >> 5;
    int g = w >> 1;            // 0..3 row group
    int h = w & 1;             // 0/1 col half
    bool isPair = unit < NP;

    const float *t1src, *t2src = nullptr, *w1src, *b1src, *g2src;
    if (isPair) {
        t1src = g_T1 + unit * FS * NH;
        t2src = g_T2 + unit * FS * NH;
        w1src = pw1 + unit * NH * NH;
        b1src = pb1 + unit * NH;
        g2src = g_gw2p + unit * NH;
    } else {
        int f = unit - NP;
        t1src = g_Tm + f * FS * NH;
        w1src = mw1 + f * NH * NH;
        b1src = mb1 + f * NH;
        g2src = g_gw2m + f * NH;
    }

    // ---- stage B combined plane: W1[k][n] -> {hi(k),hi(k+4),lo(k),lo(k+4)} ----
    for (int i = tid; i < NH * (NH / 2); i += THREADS) {
        int n = i >> 5, kw = i & 31;
        float v0 = w1src[(2 * kw) * NH + n];
        float v1 = w1src[(2 * kw + 1) * NH + n];
        uint32_t hi, lo;
        bsplit2(v0, v1, hi, lo);
        int kg = kw >> 3, c = kw & 3, sel = (kw >> 2) & 1;
        int base = (n * WST4 + kg * 4 + c) * 4;
        BCw[base + sel] = hi;
        BCw[base + 2 + sel] = lo;
    }
    if (tid < NH) { b1s[tid] = b1src[tid]; g2s[tid] = g2src[tid]; }

    // fragment address bases (constant across tiles)
    int aOff0 = (32 * g + (lane >> 2)) * AST2 + (lane & 3);          // m-tile 0
    int aOff1 = (32 * g + 16 + (lane >> 2)) * AST2 + (lane & 3);     // m-tile 1
    int bOff[4];
#pragma unroll
    for (int j = 0; j < 4; j++)
        bOff[j] = (32 * h + 8 * j + (lane >> 2)) * WST4 + (lane & 3);

    for (int t = 0; t < TILES_PER_BLOCK; t++) {
        int base = (blockIdx.y * TILES_PER_BLOCK + t) * BT;
        __syncthreads();       // B plane visible (t=0) / prev tile A consumed (t>0)

        // ---- gather: one sample per warp per round; lane = k-pair ----
        if (isPair) {
#pragma unroll
            for (int r = 0; r < 16; r++) {
                int s = r * 8 + w;
                int b = base + s;
                int2 ii = ((const int2*)pairs)[b * NP + unit];
                float2 a = ((const float2*)(t1src + ii.x * NH))[lane];
                float2 d = ((const float2*)(t2src + ii.y * NH))[lane];
                float v0 = fmaxf(a.x + d.x, 0.0f);
                float v1 = fmaxf(a.y + d.y, 0.0f);
                uint32_t hi, lo;
                bsplit2(v0, v1, hi, lo);
                AC[s * AST2 + lane] = make_uint2(hi, lo);
            }
        } else {
            int f = unit - NP;
#pragma unroll
            for (int r = 0; r < 16; r++) {
                int s = r * 8 + w;
                int b = base + s;
                int i1 = mains[b * NF + f];
                float2 a = ((const float2*)(t1src + i1 * NH))[lane];
                float v0 = fmaxf(a.x, 0.0f);
                float v1 = fmaxf(a.y, 0.0f);
                uint32_t hi, lo;
                bsplit2(v0, v1, hi, lo);
                AC[s * AST2 + lane] = make_uint2(hi, lo);
            }
        }
        __syncthreads();

        // ---- GEMM: 3-term bf16 split, m16n8k16 ----
        float acc[2][4][4];
#pragma unroll
        for (int mt = 0; mt < 2; mt++)
#pragma unroll
            for (int j = 0; j < 4; j++)
#pragma unroll
                for (int r = 0; r < 4; r++) acc[mt][j][r] = 0.0f;

#pragma unroll
        for (int ks = 0; ks < 4; ks++) {         // k chunks of 16 (8 kw words)
            int k0 = ks * 8;
            uint32_t ah[2][4], al[2][4];
#pragma unroll
            for (int mt = 0; mt < 2; mt++) {
                int ao = (mt ? aOff1 : aOff0) + k0;
                uint2 v0 = AC[ao];
                uint2 v1 = AC[ao + 8 * AST2];
                uint2 v2 = AC[ao + 4];
                uint2 v3 = AC[ao + 8 * AST2 + 4];
                ah[mt][0] = v0.x; al[mt][0] = v0.y;
                ah[mt][1] = v1.x; al[mt][1] = v1.y;
                ah[mt][2] = v2.x; al[mt][2] = v2.y;
                ah[mt][3] = v3.x; al[mt][3] = v3.y;
            }
#pragma unroll
            for (int j = 0; j < 4; j++) {
                uint4 bv = BC[bOff[j] + ks * 4];
#pragma unroll
                for (int mt = 0; mt < 2; mt++) {
                    mma_bf16(acc[mt][j][0], acc[mt][j][1], acc[mt][j][2], acc[mt][j][3],
                             ah[mt][0], ah[mt][1], ah[mt][2], ah[mt][3], bv.x, bv.y);
                    mma_bf16(acc[mt][j][0], acc[mt][j][1], acc[mt][j][2], acc[mt][j][3],
                             al[mt][0], al[mt][1], al[mt][2], al[mt][3], bv.x, bv.y);
                    mma_bf16(acc[mt][j][0], acc[mt][j][1], acc[mt][j][2], acc[mt][j][3],
                             ah[mt][0], ah[mt][1], ah[mt][2], ah[mt][3], bv.z, bv.w);
                }
            }
        }

        // ---- epilogue: +b1, relu, dot g2, lane-reduce, atomicAdd ----
#pragma unroll
        for (int mt = 0; mt < 2; mt++) {
            float s0 = 0.0f, s1 = 0.0f;
#pragma unroll
            for (int j = 0; j < 4; j++) {
                int col = 32 * h + 8 * j + 2 * (lane & 3);
                float bb0 = b1s[col], bb1 = b1s[col + 1];
                float gg0 = g2s[col], gg1 = g2s[col + 1];
                s0 = fmaf(fmaxf(acc[mt][j][0] + bb0, 0.0f), gg0, s0);
                s0 = fmaf(fmaxf(acc[mt][j][1] + bb1, 0.0f), gg1, s0);
                s1 = fmaf(fmaxf(acc[mt][j][2] + bb0, 0.0f), gg0, s1);
                s1 = fmaf(fmaxf(acc[mt][j][3] + bb1, 0.0f), gg1, s1);
            }
            s0 += __shfl_xor_sync(0xffffffffu, s0, 1);
            s0 += __shfl_xor_sync(0xffffffffu, s0, 2);
            s1 += __shfl_xor_sync(0xffffffffu, s1, 1);
            s1 += __shfl_xor_sync(0xffffffffu, s1, 2);
            if ((lane & 3) == 0) {
                int r = base + 32 * g + 16 * mt + (lane >> 2);
                atomicAdd(&out[r], s0);
                atomicAdd(&out[r + 8], s1);
            }
        }
    }
}

// ---------------- launch ----------------
extern "C" void kernel_launch(void* const* d_in, const int* in_sizes, int n_in,
                              void* d_out, int out_size)
{
    const int*   mains      = (const int*)d_in[0];
    const int*   pairs      = (const int*)d_in[1];
    const int*   pairs_list = (const int*)d_in[2];
    const int*   offsets    = (const int*)d_in[3];
    const float* embedding  = (const float*)d_in[4];
    const float* mw0        = (const float*)d_in[5];
    const float* mw1        = (const float*)d_in[6];
    const float* mw2        = (const float*)d_in[7];
    const float* mb0        = (const float*)d_in[8];
    const float* mb1        = (const float*)d_in[9];
    const float* mb2        = (const float*)d_in[10];
    const float* pw0        = (const float*)d_in[11];
    const float* pw1        = (const float*)d_in[12];
    const float* pw2        = (const float*)d_in[13];
    const float* pb0        = (const float*)d_in[14];
    const float* pb1        = (const float*)d_in[15];
    const float* pb2        = (const float*)d_in[16];
    const float* z_main     = (const float*)d_in[17];
    const float* z_pairs    = (const float*)d_in[18];
    float* out = (float*)d_out;

    static int attr_set = 0;
    const int smem_bytes = SM_WORDS * (int)sizeof(uint32_t);
    if (!attr_set) {
        cudaFuncSetAttribute(fused_pass, cudaFuncAttributeMaxDynamicSharedMemorySize, smem_bytes);
        attr_set = 1;
    }

    prelude<<<2 * NP + NF + 1, 256>>>(embedding, pairs_list, offsets,
                                      pw0, pb0, mw0, mb0,
                                      pw2, pb2, z_pairs, mw2, mb2, z_main, out);

    dim3 grid(NU, GRID_Y);
    fused_pass<<<grid, THREADS, smem_bytes>>>(mains, pairs, pw1, mw1, pb1, mb1, out);
}

// round 17
// speedup vs baseline: 2.4596x; 1.1388x over previous
#include <cuda_runtime.h>
#include <cstdint>

#define NF 32
#define NP 496
#define NU 528
#define NE 32
#define NH 64
#define FS 64
#define BATCH 2048
#define BT 128                 // samples per tile (M)
#define TILES_PER_BLOCK 4
#define GRID_Y 4               // 4 * 4 * 128 = 2048
#define THREADS 256
#define AST2 36                // A combined plane row stride (uint2 units)
#define WST4 20                // B combined plane row stride (uint4 units)

// ---------------- device scratch ----------------
__device__ __align__(128) float g_T1[NP * FS * NH];
__device__ __align__(128) float g_T2[NP * FS * NH];
__device__ __align__(128) float g_Tm[NF * FS * NH];
__device__ float g_gw2p[NP * NH];
__device__ float g_gw2m[NF * NH];

__device__ __forceinline__ float smoothz(float z) {
    if (z <= -0.5f) return 0.0f;
    if (z >= 0.5f) return 1.0f;
    return -2.0f * z * z * z + 1.5f * z + 0.5f;
}

// pack two fp32 into bf16x2 hi-part and residual lo-part words
__device__ __forceinline__ void bsplit2(float a0, float a1, uint32_t& hi, uint32_t& lo) {
    asm("cvt.rn.bf16x2.f32 %0, %2, %1;" : "=r"(hi) : "f"(a0), "f"(a1));
    float h0 = __uint_as_float(hi << 16);
    float h1 = __uint_as_float(hi & 0xffff0000u);
    float l0 = a0 - h0, l1 = a1 - h1;
    asm("cvt.rn.bf16x2.f32 %0, %2, %1;" : "=r"(lo) : "f"(l0), "f"(l1));
}

__device__ __forceinline__ void mma_bf16(float& d0, float& d1, float& d2, float& d3,
                                         uint32_t a0, uint32_t a1, uint32_t a2, uint32_t a3,
                                         uint32_t b0, uint32_t b1) {
    asm("mma.sync.aligned.m16n8k16.row.col.f32.bf16.bf16.f32 "
        "{%0,%1,%2,%3}, {%4,%5,%6,%7}, {%8,%9}, {%0,%1,%2,%3};"
        : "+f"(d0), "+f"(d1), "+f"(d2), "+f"(d3)
        : "r"(a0), "r"(a1), "r"(a2), "r"(a3), "r"(b0), "r"(b1));
}

// ---------------- kernel 1: merged prelude ----------------
// blocks 0..1023: layer-0 lookup tables (4v x 4j register tiles, vector I/O)
// block 1024: gated layer-2 weights + bias constant + output init
__global__ __launch_bounds__(256) void prelude(
    const float* __restrict__ emb,
    const int* __restrict__ pairs_list,
    const int* __restrict__ offsets,
    const float* __restrict__ pw0, const float* __restrict__ pb0,
    const float* __restrict__ mw0, const float* __restrict__ mb0,
    const float* __restrict__ pw2, const float* __restrict__ pb2,
    const float* __restrict__ zp,
    const float* __restrict__ mw2, const float* __restrict__ mb2,
    const float* __restrict__ zm,
    float* __restrict__ out)
{
    int bid = blockIdx.x;
    int tid = threadIdx.x;

    if (bid >= 2 * NP + NF) {
        // ---- gates + constant + out init ----
        __shared__ float red[256];
        for (int i = tid; i < NP * NH; i += 256) g_gw2p[i] = pw2[i] * smoothz(zp[i >> 6]);
        for (int i = tid; i < NF * NH; i += 256) g_gw2m[i] = mw2[i] * smoothz(zm[i >> 6]);
        float c = 0.0f;
        for (int p = tid; p < NP; p += 256) c += pb2[p] * smoothz(zp[p]);
        for (int f = tid; f < NF; f += 256) c += mb2[f] * smoothz(zm[f]);
        red[tid] = c;
        __syncthreads();
        for (int o = 128; o > 0; o >>= 1) {
            if (tid < o) red[tid] += red[tid + o];
            __syncthreads();
        }
        float C = red[0];
        for (int i = tid; i < BATCH; i += 256) out[i] = C;
        return;
    }

    // ---- table block ----
    __shared__ float Es[FS * NE];
    __shared__ float Ws[NE * NH];

    const float* wsrc;
    const float* bias = nullptr;
    float* dst;
    int embRow0;

    if (bid < NP) {
        int p = bid;
        embRow0 = offsets[pairs_list[2 * p]];
        wsrc = pw0 + (p * 64 + 0) * NH;
        bias = pb0 + p * NH;
        dst = g_T1 + p * FS * NH;
    } else if (bid < 2 * NP) {
        int p = bid - NP;
        embRow0 = offsets[pairs_list[2 * p + 1]];
        wsrc = pw0 + (p * 64 + 32) * NH;
        dst = g_T2 + p * FS * NH;
    } else {
        int f = bid - 2 * NP;
        embRow0 = f * FS;
        wsrc = mw0 + f * NE * NH;
        bias = mb0 + f * NH;
        dst = g_Tm + f * FS * NH;
    }

    {
        const float4* es = (const float4*)(emb + embRow0 * NE);
        for (int i = tid; i < FS * NE / 4; i += 256) ((float4*)Es)[i] = es[i];
        const float4* ws = (const float4*)wsrc;
        for (int i = tid; i < NE * NH / 4; i += 256) ((float4*)Ws)[i] = ws[i];
    }
    __syncthreads();

    // 4v x 4j register tile per thread: per e = 4 scalar A loads (broadcast)
    // + 1 float4 W load for 16 FMAs.
    int v0 = (tid >> 4) << 2;       // 0,4,...,60
    int j0 = (tid & 15) << 2;       // 0,4,...,60
    float acc[4][4];
#pragma unroll
    for (int c = 0; c < 4; c++) {
        float bv = bias ? bias[j0 + c] : 0.0f;
#pragma unroll
        for (int r = 0; r < 4; r++) acc[r][c] = bv;
    }
    for (int e = 0; e < NE; e++) {
        float4 wv = *(const float4*)&Ws[e * NH + j0];
        float a0 = Es[(v0 + 0) * NE + e];
        float a1 = Es[(v0 + 1) * NE + e];
        float a2 = Es[(v0 + 2) * NE + e];
        float a3 = Es[(v0 + 3) * NE + e];
        acc[0][0] = fmaf(a0, wv.x, acc[0][0]); acc[0][1] = fmaf(a0, wv.y, acc[0][1]);
        acc[0][2] = fmaf(a0, wv.z, acc[0][2]); acc[0][3] = fmaf(a0, wv.w, acc[0][3]);
        acc[1][0] = fmaf(a1, wv.x, acc[1][0]); acc[1][1] = fmaf(a1, wv.y, acc[1][1]);
        acc[1][2] = fmaf(a1, wv.z, acc[1][2]); acc[1][3] = fmaf(a1, wv.w, acc[1][3]);
        acc[2][0] = fmaf(a2, wv.x, acc[2][0]); acc[2][1] = fmaf(a2, wv.y, acc[2][1]);
        acc[2][2] = fmaf(a2, wv.z, acc[2][2]); acc[2][3] = fmaf(a2, wv.w, acc[2][3]);
        acc[3][0] = fmaf(a3, wv.x, acc[3][0]); acc[3][1] = fmaf(a3, wv.y, acc[3][1]);
        acc[3][2] = fmaf(a3, wv.z, acc[3][2]); acc[3][3] = fmaf(a3, wv.w, acc[3][3]);
    }
#pragma unroll
    for (int r = 0; r < 4; r++) {
        float4 vv = make_float4(acc[r][0], acc[r][1], acc[r][2], acc[r][3]);
        *(float4*)&dst[(v0 + r) * NH + j0] = vv;
    }
}

// ---------------- kernel 2: fused main pass (bf16 m16n8k16, interleaved planes) -
// 256 threads = 8 warps, 3 CTAs/SM. Tile: 128 samples x 64 cols.
// A combined plane: uint2 {hi,lo} per (s,kw), stride 36 uint2 (conflict-free).
// B combined plane: uint4 {hi(k),hi(k+4),lo(k),lo(k+4)} per (n,kg,c), stride 20 uint4.
#define SM_AC 0
#define SM_BC (SM_AC + BT * AST2 * 2)        //  9216 words
#define SM_B1 (SM_BC + NH * WST4 * 4)        // 14336
#define SM_G2 (SM_B1 + NH)                   // 14400
#define SM_WORDS (SM_G2 + NH)                // 14464 words = 57856 B -> 3 CTAs/SM

__global__ __launch_bounds__(THREADS, 3) void fused_pass(
    const int* __restrict__ mains, const int* __restrict__ pairs,
    const float* __restrict__ pw1, const float* __restrict__ mw1,
    const float* __restrict__ pb1, const float* __restrict__ mb1,
    float* __restrict__ out)
{
    extern __shared__ uint32_t smw[];
    uint2* AC = (uint2*)(smw + SM_AC);
    uint4* BC = (uint4*)(smw + SM_BC);
    uint32_t* BCw = smw + SM_BC;
    float* b1s = (float*)(smw + SM_B1);
    float* g2s = (float*)(smw + SM_G2);

    int unit = blockIdx.x;
    int tid = threadIdx.x;
    int lane = tid & 31;
    int w = tid >> 5;
    int g = w >> 1;            // 0..3 row group
    int h = w & 1;             // 0/1 col half
    bool isPair = unit < NP;

    const float *t1src, *t2src = nullptr, *w1src, *b1src, *g2src;
    if (isPair) {
        t1src = g_T1 + unit * FS * NH;
        t2src = g_T2 + unit * FS * NH;
        w1src = pw1 + unit * NH * NH;
        b1src = pb1 + unit * NH;
        g2src = g_gw2p + unit * NH;
    } else {
        int f = unit - NP;
        t1src = g_Tm + f * FS * NH;
        w1src = mw1 + f * NH * NH;
        b1src = mb1 + f * NH;
        g2src = g_gw2m + f * NH;
    }

    // ---- stage B combined plane: W1[k][n] -> {hi(k),hi(k+4),lo(k),lo(k+4)} ----
    for (int i = tid; i < NH * (NH / 2); i += THREADS) {
        int n = i >> 5, kw = i & 31;
        float v0 = w1src[(2 * kw) * NH + n];
        float v1 = w1src[(2 * kw + 1) * NH + n];
        uint32_t hi, lo;
        bsplit2(v0, v1, hi, lo);
        int kg = kw >> 3, c = kw & 3, sel = (kw >> 2) & 1;
        int base = (n * WST4 + kg * 4 + c) * 4;
        BCw[base + sel] = hi;
        BCw[base + 2 + sel] = lo;
    }
    if (tid < NH) { b1s[tid] = b1src[tid]; g2s[tid] = g2src[tid]; }

    // fragment address bases (constant across tiles)
    int aOff0 = (32 * g + (lane >> 2)) * AST2 + (lane & 3);          // m-tile 0
    int aOff1 = (32 * g + 16 + (lane >> 2)) * AST2 + (lane & 3);     // m-tile 1
    int bOff[4];
#pragma unroll
    for (int j = 0; j < 4; j++)
        bOff[j] = (32 * h + 8 * j + (lane >> 2)) * WST4 + (lane & 3);

    for (int t = 0; t < TILES_PER_BLOCK; t++) {
        int base = (blockIdx.y * TILES_PER_BLOCK + t) * BT;
        __syncthreads();       // B plane visible (t=0) / prev tile A consumed (t>0)

        // ---- gather: one sample per warp per round; lane = k-pair ----
        if (isPair) {
#pragma unroll
            for (int r = 0; r < 16; r++) {
                int s = r * 8 + w;
                int b = base + s;
                int2 ii = ((const int2*)pairs)[b * NP + unit];
                float2 a = ((const float2*)(t1src + ii.x * NH))[lane];
                float2 d = ((const float2*)(t2src + ii.y * NH))[lane];
                float v0 = fmaxf(a.x + d.x, 0.0f);
                float v1 = fmaxf(a.y + d.y, 0.0f);
                uint32_t hi, lo;
                bsplit2(v0, v1, hi, lo);
                AC[s * AST2 + lane] = make_uint2(hi, lo);
            }
        } else {
            int f = unit - NP;
#pragma unroll
            for (int r = 0; r < 16; r++) {
                int s = r * 8 + w;
                int b = base + s;
                int i1 = mains[b * NF + f];
                float2 a = ((const float2*)(t1src + i1 * NH))[lane];
                float v0 = fmaxf(a.x, 0.0f);
                float v1 = fmaxf(a.y, 0.0f);
                uint32_t hi, lo;
                bsplit2(v0, v1, hi, lo);
                AC[s * AST2 + lane] = make_uint2(hi, lo);
            }
        }
        __syncthreads();

        // ---- GEMM: 3-term bf16 split, m16n8k16 ----
        float acc[2][4][4];
#pragma unroll
        for (int mt = 0; mt < 2; mt++)
#pragma unroll
            for (int j = 0; j < 4; j++)
#pragma unroll
                for (int r = 0; r < 4; r++) acc[mt][j][r] = 0.0f;

#pragma unroll
        for (int ks = 0; ks < 4; ks++) {         // k chunks of 16 (8 kw words)
            int k0 = ks * 8;
            uint32_t ah[2][4], al[2][4];
#pragma unroll
            for (int mt = 0; mt < 2; mt++) {
                int ao = (mt ? aOff1 : aOff0) + k0;
                uint2 v0 = AC[ao];
                uint2 v1 = AC[ao + 8 * AST2];
                uint2 v2 = AC[ao + 4];
                uint2 v3 = AC[ao + 8 * AST2 + 4];
                ah[mt][0] = v0.x; al[mt][0] = v0.y;
                ah[mt][1] = v1.x; al[mt][1] = v1.y;
                ah[mt][2] = v2.x; al[mt][2] = v2.y;
                ah[mt][3] = v3.x; al[mt][3] = v3.y;
            }
#pragma unroll
            for (int j = 0; j < 4; j++) {
                uint4 bv = BC[bOff[j] + ks * 4];
#pragma unroll
                for (int mt = 0; mt < 2; mt++) {
                    mma_bf16(acc[mt][j][0], acc[mt][j][1], acc[mt][j][2], acc[mt][j][3],
                             ah[mt][0], ah[mt][1], ah[mt][2], ah[mt][3], bv.x, bv.y);
                    mma_bf16(acc[mt][j][0], acc[mt][j][1], acc[mt][j][2], acc[mt][j][3],
                             al[mt][0], al[mt][1], al[mt][2], al[mt][3], bv.x, bv.y);
                    mma_bf16(acc[mt][j][0], acc[mt][j][1], acc[mt][j][2], acc[mt][j][3],
                             ah[mt][0], ah[mt][1], ah[mt][2], ah[mt][3], bv.z, bv.w);
                }
            }
        }

        // ---- epilogue: +b1, relu, dot g2, lane-reduce, atomicAdd ----
#pragma unroll
        for (int mt = 0; mt < 2; mt++) {
            float s0 = 0.0f, s1 = 0.0f;
#pragma unroll
            for (int j = 0; j < 4; j++) {
                int col = 32 * h + 8 * j + 2 * (lane & 3);
                float bb0 = b1s[col], bb1 = b1s[col + 1];
                float gg0 = g2s[col], gg1 = g2s[col + 1];
                s0 = fmaf(fmaxf(acc[mt][j][0] + bb0, 0.0f), gg0, s0);
                s0 = fmaf(fmaxf(acc[mt][j][1] + bb1, 0.0f), gg1, s0);
                s1 = fmaf(fmaxf(acc[mt][j][2] + bb0, 0.0f), gg0, s1);
                s1 = fmaf(fmaxf(acc[mt][j][3] + bb1, 0.0f), gg1, s1);
            }
            s0 += __shfl_xor_sync(0xffffffffu, s0, 1);
            s0 += __shfl_xor_sync(0xffffffffu, s0, 2);
            s1 += __shfl_xor_sync(0xffffffffu, s1, 1);
            s1 += __shfl_xor_sync(0xffffffffu, s1, 2);
            if ((lane & 3) == 0) {
                int r = base + 32 * g + 16 * mt + (lane >> 2);
                atomicAdd(&out[r], s0);
                atomicAdd(&out[r + 8], s1);
            }
        }
    }
}

// ---------------- launch ----------------
extern "C" void kernel_launch(void* const* d_in, const int* in_sizes, int n_in,
                              void* d_out, int out_size)
{
    const int*   mains      = (const int*)d_in[0];
    const int*   pairs      = (const int*)d_in[1];
    const int*   pairs_list = (const int*)d_in[2];
    const int*   offsets    = (const int*)d_in[3];
    const float* embedding  = (const float*)d_in[4];
    const float* mw0        = (const float*)d_in[5];
    const float* mw1        = (const float*)d_in[6];
    const float* mw2        = (const float*)d_in[7];
    const float* mb0        = (const float*)d_in[8];
    const float* mb1        = (const float*)d_in[9];
    const float* mb2        = (const float*)d_in[10];
    const float* pw0        = (const float*)d_in[11];
    const float* pw1        = (const float*)d_in[12];
    const float* pw2        = (const float*)d_in[13];
    const float* pb0        = (const float*)d_in[14];
    const float* pb1        = (const float*)d_in[15];
    const float* pb2        = (const float*)d_in[16];
    const float* z_main     = (const float*)d_in[17];
    const float* z_pairs    = (const float*)d_in[18];
    float* out = (float*)d_out;

    static int attr_set = 0;
    const int smem_bytes = SM_WORDS * (int)sizeof(uint32_t);
    if (!attr_set) {
        cudaFuncSetAttribute(fused_pass, cudaFuncAttributeMaxDynamicSharedMemorySize, smem_bytes);
        attr_set = 1;
    }

    prelude<<<2 * NP + NF + 1, 256>>>(embedding, pairs_list, offsets,
                                      pw0, pb0, mw0, mb0,
                                      pw2, pb2, z_pairs, mw2, mb2, z_main, out);

    dim3 grid(NU, GRID_Y);
    fused_pass<<<grid, THREADS, smem_bytes>>>(mains, pairs, pw1, mw1, pb1, mb1, out);
}